// round 5
// baseline (speedup 1.0000x reference)
#include <cuda_runtime.h>

// LineSpectralPairsStabilityCheck: (256, 4096, 33) fp32, 1,048,576 rows.
// Per row: keep [0]; 4 passes of {31-step neighbor-separation scan + clip}
// on [1..32]. Issue-bound per ncu -> pack 2 rows/thread with f32x2 packed
// arithmetic (fma.rn.f32x2 / add.rn.f32x2 -> FFMA2/FADD2), clip folded into
// scan output (off the carried dependency chain).

#define W 33
#define THREADS 128
#define ROWS_PER_BLOCK 256
#define TILE_ELEMS (ROWS_PER_BLOCK * W)   // 8448 floats = 33792 B smem
#define TILE_VEC4 (TILE_ELEMS / 4)        // 2112 float4

__device__ __forceinline__ float2 fma2(float2 a, float2 b, float2 c) {
    float2 d;
    asm("{\n\t"
        ".reg .b64 ra, rb, rc, rd;\n\t"
        "mov.b64 ra, {%2, %3};\n\t"
        "mov.b64 rb, {%4, %5};\n\t"
        "mov.b64 rc, {%6, %7};\n\t"
        "fma.rn.f32x2 rd, ra, rb, rc;\n\t"
        "mov.b64 {%0, %1}, rd;\n\t"
        "}"
        : "=f"(d.x), "=f"(d.y)
        : "f"(a.x), "f"(a.y), "f"(b.x), "f"(b.y), "f"(c.x), "f"(c.y));
    return d;
}

__device__ __forceinline__ float2 add2(float2 a, float2 b) {
    float2 d;
    asm("{\n\t"
        ".reg .b64 ra, rb, rd;\n\t"
        "mov.b64 ra, {%2, %3};\n\t"
        "mov.b64 rb, {%4, %5};\n\t"
        "add.rn.f32x2 rd, ra, rb;\n\t"
        "mov.b64 {%0, %1}, rd;\n\t"
        "}"
        : "=f"(d.x), "=f"(d.y)
        : "f"(a.x), "f"(a.y), "f"(b.x), "f"(b.y));
    return d;
}

__global__ void __launch_bounds__(THREADS)
lsp_stability_kernel(const float* __restrict__ in, float* __restrict__ out)
{
    __shared__ float sm[TILE_ELEMS];

    const int t = threadIdx.x;
    const long long base = (long long)blockIdx.x * TILE_ELEMS;

    // ---- coalesced vectorized streaming load of the block tile ----
    const float4* __restrict__ in4 = (const float4*)(in + base);
    float4* sm4 = (float4*)sm;
    for (int i = t; i < TILE_VEC4; i += THREADS)
        sm4[i] = __ldcs(&in4[i]);
    __syncthreads();

    // ---- thread t owns rows t and t+128 of the tile ----
    // Bank pattern (33t + i) mod 32 = (t + i) mod 32: conflict-free; the
    // second row adds 33*128 = 4224 == 0 mod 32, also conflict-free.
    // Channel 0 (K) is never touched: it stays in smem and passes through.
    float2 v[W];   // only [1..32] used; v[0] dead -> not allocated
    #pragma unroll
    for (int i = 1; i < W; i++) {
        v[i].x = sm[t * W + i];
        v[i].y = sm[(t + THREADS) * W + i];
    }

    const float min_d = (float)(0.01 * 3.14159265358979323846 / 33.0);
    const float hi    = 3.14159265358979323846f - min_d;
    const float2 mind2 = make_float2(min_d, min_d);
    const float2 neg1  = make_float2(-1.0f, -1.0f);
    const float2 negh  = make_float2(-0.5f, -0.5f);
    const float2 half  = make_float2( 0.5f,  0.5f);

    #pragma unroll
    for (int it = 0; it < 4; it++) {
        float2 c = v[1];
        #pragma unroll
        for (int i = 2; i <= 32; i++) {
            float2 nxt = v[i];
            float2 tt = fma2(nxt, neg1, c);     // c - nxt
            float2 u  = add2(tt, mind2);        // min_d - (nxt - c)
            float2 s;                           // s = max(u, 0)   (s = 2*shift)
            s.x = fmaxf(u.x, 0.0f);
            s.y = fmaxf(u.y, 0.0f);
            float2 o = fma2(s, negh, c);        // c - 0.5*s
            // clip folded here: o is final for this pass, off the c-chain
            o.x = fminf(fmaxf(o.x, min_d), hi);
            o.y = fminf(fmaxf(o.y, min_d), hi);
            v[i - 1] = o;
            c = fma2(s, half, nxt);             // nxt + 0.5*s (carried unclipped)
        }
        v[32].x = fminf(fmaxf(c.x, min_d), hi);
        v[32].y = fminf(fmaxf(c.y, min_d), hi);
    }

    // ---- write rows back to private smem cells (channel 0 untouched) ----
    #pragma unroll
    for (int i = 1; i < W; i++) {
        sm[t * W + i]             = v[i].x;
        sm[(t + THREADS) * W + i] = v[i].y;
    }
    __syncthreads();

    // ---- coalesced vectorized streaming store ----
    float4* __restrict__ out4 = (float4*)(out + base);
    for (int i = t; i < TILE_VEC4; i += THREADS)
        __stcs(&out4[i], sm4[i]);
}

extern "C" void kernel_launch(void* const* d_in, const int* in_sizes, int n_in,
                              void* d_out, int out_size)
{
    const float* in = (const float*)d_in[0];
    float* out = (float*)d_out;

    const int total = in_sizes[0];                 // 256*4096*33 = 34,603,008
    const int rows = total / W;                    // 1,048,576
    const int blocks = rows / ROWS_PER_BLOCK;      // 4096 (exact)

    lsp_stability_kernel<<<blocks, THREADS>>>(in, out);
}

// round 6
// speedup vs baseline: 1.6028x; 1.6028x over previous
#include <cuda_runtime.h>

// LineSpectralPairsStabilityCheck: (256, 4096, 33) fp32, 1,048,576 rows.
// Per row: keep [0]; 4 passes of {31-step neighbor-separation scan + clip}.
// Issue/ILP-bound. 1 thread per row (44 regs -> occ ~57%), smem-staged
// coalesced float4 global I/O. Scan restructured: off-chain m = min_d - nxt
// shortens the carried chain to FADD->FMNMX->FFMA; clip folded into the scan
// as off-chain work so the scheduler can interleave it (and overlap passes).

#define W 33
#define ROWS_PER_BLOCK 128
#define TILE_ELEMS (ROWS_PER_BLOCK * W)   // 4224 floats = 16896 B
#define TILE_VEC4 (TILE_ELEMS / 4)        // 1056

__global__ void __launch_bounds__(ROWS_PER_BLOCK)
lsp_stability_kernel(const float* __restrict__ in, float* __restrict__ out)
{
    __shared__ float sm[TILE_ELEMS];

    const int t = threadIdx.x;
    const long long base = (long long)blockIdx.x * TILE_ELEMS;

    // ---- coalesced vectorized streaming load of the block tile ----
    const float4* __restrict__ in4 = (const float4*)(in + base);
    float4* sm4 = (float4*)sm;
    #pragma unroll
    for (int i = t; i < TILE_VEC4; i += ROWS_PER_BLOCK)
        sm4[i] = __ldcs(&in4[i]);
    __syncthreads();

    // ---- each thread owns one row (stride-33 smem: conflict-free) ----
    // Channel 0 (K) passes through smem untouched.
    float v[W];   // v[0] unused
    #pragma unroll
    for (int i = 1; i < W; i++)
        v[i] = sm[t * W + i];

    const float pi_f  = 3.14159265358979323846f;
    const float min_d = 0.01f * pi_f / 33.0f;   // RATE * pi / (LSP_ORDER + 1)
    const float hi    = pi_f - min_d;

    #pragma unroll
    for (int it = 0; it < 4; it++) {
        // scan over v[1..32] with clip folded in.
        // chain per step: u = c + m (FADD) -> s = max(u,0) (FMNMX)
        //              -> c = fma(s, 0.5, nxt) (FFMA)
        // off-chain:    m = min_d - nxt;  o = fma(s,-0.5,c); 2x clip FMNMX
        float c = v[1];
        #pragma unroll
        for (int i = 2; i <= 32; i++) {
            float nxt = v[i];
            float m = min_d - nxt;            // off-chain, available early
            float u = c + m;                  // chain
            float s = fmaxf(u, 0.0f);         // chain
            float o = fmaf(s, -0.5f, c);      // off-chain output
            o = fmaxf(o, min_d);
            v[i - 1] = fminf(o, hi);          // final for this pass
            c = fmaf(s, 0.5f, nxt);           // chain (carried unclipped)
        }
        v[32] = fminf(fmaxf(c, min_d), hi);
    }

    // ---- write row back to private smem region ----
    #pragma unroll
    for (int i = 1; i < W; i++)
        sm[t * W + i] = v[i];
    __syncthreads();

    // ---- coalesced vectorized streaming store ----
    float4* __restrict__ out4 = (float4*)(out + base);
    #pragma unroll
    for (int i = t; i < TILE_VEC4; i += ROWS_PER_BLOCK)
        __stcs(&out4[i], sm4[i]);
}

extern "C" void kernel_launch(void* const* d_in, const int* in_sizes, int n_in,
                              void* d_out, int out_size)
{
    const float* in = (const float*)d_in[0];
    float* out = (float*)d_out;

    const int total = in_sizes[0];            // 256*4096*33 = 34,603,008
    const int rows = total / W;               // 1,048,576
    const int blocks = rows / ROWS_PER_BLOCK; // 8192 (exact)

    lsp_stability_kernel<<<blocks, ROWS_PER_BLOCK>>>(in, out);
}